// round 1
// baseline (speedup 1.0000x reference)
#include <cuda_runtime.h>
#include <cuda_bf16.h>

// Problem constants
#define IC   256
#define OC   128
#define HI   32
#define WI   32
#define NB   32
#define OH   64
#define OW   64

// Reorganized weights: [parity p=rh*2+rw][ic][tap=j*2+i][oc]
// tap (j,i) maps to W[oc][ic][2j+rh][2i+rw]
__device__ float g_Wt[4 * IC * 4 * OC];  // 2 MB scratch

__global__ void wt_transform_kernel(const float* __restrict__ W) {
    int idx = blockIdx.x * blockDim.x + threadIdx.x;  // 2^19 total
    int oc  = idx & 127;
    int tap = (idx >> 7) & 3;
    int ic  = (idx >> 9) & 255;
    int p   = idx >> 17;
    int kh = 2 * (tap >> 1) + (p >> 1);
    int kw = 2 * (tap & 1) + (p & 1);
    g_Wt[idx] = W[((oc * IC + ic) * 4 + kh) * 4 + kw];
}

// Per parity class p=(rh,rw):
//   y[b, oc, 2a+rh, 2c+rw] = bias[oc]
//     + sum_ic sum_{j,i in {0,1}} x[b, ic, a+j+rh-1, c+i+rw-1] * Wt[p][ic][j*2+i][oc]
// Block: all 128 oc x 8x8 (a,c) tile, one batch, one parity. 256 threads.
// Thread: 8 oc x 2x2 spatial register tile.
__global__ __launch_bounds__(256)
void tconv_kernel(const float* __restrict__ x,
                  const float* __restrict__ bias,
                  float* __restrict__ y) {
    const int p  = blockIdx.z;
    const int rh = p >> 1, rw = p & 1;
    const int b  = blockIdx.y;
    const int ta = (blockIdx.x >> 2) * 8;   // a-tile origin in [0,32)
    const int tc = (blockIdx.x & 3) * 8;    // c-tile origin in [0,32)

    __shared__ float As[8 * 4 * 128];   // [ic_l][tap][oc]  16 KB
    __shared__ float Bs[8 * 9 * 12];    // [ic_l][row 0..8][col 0..8], row stride 12 (conflict-free)

    const int tid = threadIdx.x;
    const int ty  = tid >> 4;           // 0..15 -> oc group
    const int tx  = tid & 15;           // 0..15 -> spatial group
    const int m0  = ty * 8;
    const int ag  = tx >> 2;            // 0..3
    const int cg  = tx & 3;             // 0..3

    float acc[8][4];
    #pragma unroll
    for (int m = 0; m < 8; m++)
        #pragma unroll
        for (int s = 0; s < 4; s++) acc[m][s] = 0.f;

    const float* xb      = x + (size_t)b * IC * HI * WI;
    const float* wt_base = g_Wt + (size_t)p * IC * 4 * OC;

    for (int ic0 = 0; ic0 < IC; ic0 += 8) {
        // ---- Load A: contiguous 4096 floats (8 ic x 4 taps x 128 oc) via float4
        {
            const float4* src = (const float4*)(wt_base + (size_t)ic0 * 4 * OC);
            float4* dst = (float4*)As;
            #pragma unroll
            for (int i = 0; i < 4; i++)
                dst[tid + i * 256] = src[tid + i * 256];
        }
        // ---- Load B: 8 ic x 9x9 input window (zero-padded at borders)
        for (int i = tid; i < 8 * 81; i += 256) {
            int icl = i / 81;
            int rem = i - icl * 81;
            int r   = rem / 9;
            int cc  = rem - r * 9;
            int ih  = ta + rh - 1 + r;
            int iw  = tc + rw - 1 + cc;
            float v = 0.f;
            if ((unsigned)ih < HI && (unsigned)iw < WI)
                v = xb[(size_t)(ic0 + icl) * (HI * WI) + ih * WI + iw];
            Bs[icl * 108 + r * 12 + cc] = v;
        }
        __syncthreads();

        #pragma unroll
        for (int icl = 0; icl < 8; icl++) {
            // 3x3 input patch covers all 4 taps for this thread's 2x2 outputs
            float b9[3][3];
            #pragma unroll
            for (int rr = 0; rr < 3; rr++)
                #pragma unroll
                for (int c2 = 0; c2 < 3; c2++)
                    b9[rr][c2] = Bs[icl * 108 + (2 * ag + rr) * 12 + 2 * cg + c2];

            const float* asl = As + icl * 512;
            #pragma unroll
            for (int tap = 0; tap < 4; tap++) {
                const int j = tap >> 1, ii = tap & 1;
                float4 a0 = *(const float4*)(asl + tap * 128 + m0);
                float4 a1 = *(const float4*)(asl + tap * 128 + m0 + 4);
                float a8[8] = {a0.x, a0.y, a0.z, a0.w, a1.x, a1.y, a1.z, a1.w};
                #pragma unroll
                for (int mm = 0; mm < 8; mm++)
                    #pragma unroll
                    for (int da = 0; da < 2; da++)
                        #pragma unroll
                        for (int dc = 0; dc < 2; dc++)
                            acc[mm][da * 2 + dc] += a8[mm] * b9[da + j][dc + ii];
            }
        }
        __syncthreads();
    }

    // ---- Epilogue: add bias, scatter to strided output positions
    #pragma unroll
    for (int mm = 0; mm < 8; mm++) {
        const int oc = m0 + mm;
        const float bv = bias[oc];
        #pragma unroll
        for (int da = 0; da < 2; da++) {
            const int oh = 2 * (ta + 2 * ag + da) + rh;
            #pragma unroll
            for (int dc = 0; dc < 2; dc++) {
                const int ow = 2 * (tc + 2 * cg + dc) + rw;
                y[(((size_t)b * OC + oc) * OH + oh) * OW + ow] = acc[mm][da * 2 + dc] + bv;
            }
        }
    }
}

extern "C" void kernel_launch(void* const* d_in, const int* in_sizes, int n_in,
                              void* d_out, int out_size) {
    const float* x    = (const float*)d_in[0];
    const float* W    = (const float*)d_in[1];
    const float* bias = (const float*)d_in[2];
    float* y = (float*)d_out;

    wt_transform_kernel<<<(4 * IC * 4 * OC) / 256, 256>>>(W);

    dim3 grid(16, NB, 4);  // 16 spatial tiles x 32 batches x 4 parity classes
    tconv_kernel<<<grid, 256>>>(x, bias, y);
}

// round 11
// speedup vs baseline: 2.6350x; 2.6350x over previous
#include <cuda_runtime.h>
#include <cuda_bf16.h>
#include <cstdint>

#define IC    256
#define OC    128
#define HIN   32
#define WIN_  32
#define NB    32
#define ICPC  8
#define NCHUNK 32
#define ROWB  80          // bytes per k-row: 32 bf16 = 64B + 16B pad (conflict-free ldmatrix)

// ---- dynamic SMEM layout (bytes) ----
#define SM_A    0                      // [buf][hl][128][ROWB] : buf*20480 + hl*10240
#define SM_B    40960                  // [buf][hl][256][ROWB] : buf*40960 + hl*20480
#define SM_WIN  122880                 // 8 ic x 9 rows x 36 floats
#define WIN_ROWF 36
#define SMEM_TOTAL (SM_WIN + ICPC*9*WIN_ROWF*4)   // 133248

// Pre-laid-out A: [p][chunk][128 oc][ROWB]  (k-major bf16 rows, 16B tail pad unused)
__device__ __align__(16) unsigned char g_Ah[4 * 32 * 128 * ROWB];
__device__ __align__(16) unsigned char g_Al[4 * 32 * 128 * ROWB];

// ---------------- asm helpers ----------------
__device__ __forceinline__ uint32_t smem_u32(const void* p) {
    uint32_t a;
    asm("{ .reg .u64 t; cvta.to.shared.u64 t, %1; cvt.u32.u64 %0, t; }" : "=r"(a) : "l"(p));
    return a;
}
__device__ __forceinline__ void cp16(uint32_t d, const void* s) {
    asm volatile("cp.async.cg.shared.global [%0], [%1], 16;" :: "r"(d), "l"(s) : "memory");
}
__device__ __forceinline__ void cp8z(uint32_t d, const void* s, int sz) {
    asm volatile("cp.async.ca.shared.global [%0], [%1], 8, %2;" :: "r"(d), "l"(s), "r"(sz) : "memory");
}
__device__ __forceinline__ void cp_commit() { asm volatile("cp.async.commit_group;" ::: "memory"); }
template <int N> __device__ __forceinline__ void cp_wait() {
    asm volatile("cp.async.wait_group %0;" :: "n"(N) : "memory");
}
__device__ __forceinline__ uint32_t bf16x2_of(float lo, float hi) {
    uint32_t r;
    asm("cvt.rn.bf16x2.f32 %0, %1, %2;" : "=r"(r) : "f"(hi), "f"(lo));
    return r;
}
#define LDSM4(r, a)                                                              \
    asm volatile("ldmatrix.sync.aligned.m8n8.x4.shared.b16 {%0,%1,%2,%3}, [%4];" \
                 : "=r"((r)[0]), "=r"((r)[1]), "=r"((r)[2]), "=r"((r)[3])        \
                 : "r"(a))
#define MMA(c, a, b0, b1)                                                        \
    asm volatile("mma.sync.aligned.m16n8k16.row.col.f32.bf16.bf16.f32 "          \
                 "{%0,%1,%2,%3},{%4,%5,%6,%7},{%8,%9},{%0,%1,%2,%3};"            \
                 : "+f"((c)[0]), "+f"((c)[1]), "+f"((c)[2]), "+f"((c)[3])        \
                 : "r"((a)[0]), "r"((a)[1]), "r"((a)[2]), "r"((a)[3]),           \
                   "r"(b0), "r"(b1))

// ---------------- weight transform ----------------
// A[oc][k] = W[oc][ck*8+icl][2j+rh][2i+rw], k = icl*4 + (j*2+i). hi/lo bf16 split.
__global__ void wt_kernel(const float* __restrict__ W) {
    int idx = blockIdx.x * blockDim.x + threadIdx.x;   // 2^19
    int k  = idx & 31;
    int oc = (idx >> 5) & 127;
    int ck = (idx >> 12) & 31;
    int p  = idx >> 17;
    int tap = k & 3, icl = k >> 2;
    int ic = ck * ICPC + icl;
    int kh = 2 * (tap >> 1) + (p >> 1);
    int kw = 2 * (tap & 1) + (p & 1);
    float v = W[((oc * IC + ic) * 4 + kh) * 4 + kw];
    __nv_bfloat16 h = __float2bfloat16(v);
    __nv_bfloat16 l = __float2bfloat16(v - __bfloat162float(h));
    size_t off = ((size_t)(p * 32 + ck) * 128 + oc) * ROWB + k * 2;
    *(__nv_bfloat16*)(g_Ah + off) = h;
    *(__nv_bfloat16*)(g_Al + off) = l;
}

// ---------------- main kernel ----------------
// grid (4 a-blocks, 32 batches, 4 parities), 256 threads = 8 warps (2 m x 4 n),
// warp tile 64x64.  D[oc=128][n=256], n = a_l*32 + c_l.
__global__ __launch_bounds__(256, 1)
void tconv_hmma(const float* __restrict__ x,
                const float* __restrict__ bias,
                float* __restrict__ y) {
    extern __shared__ char smem[];
    const uint32_t sb = smem_u32(smem);
    const int tid = threadIdx.x;
    const int warp = tid >> 5, lane = tid & 31;
    const int wm = warp & 1, wn = warp >> 1;
    const int p = blockIdx.z, b = blockIdx.y;
    const int rh = p >> 1, rw = p & 1;
    const int ta = blockIdx.x * 8;

    const int g = lane >> 3, r = lane & 7;
    const uint32_t a_lane = (uint32_t)(((g & 1) * 8 + r) * ROWB + (g >> 1) * 16);
    const uint32_t b_lane = (uint32_t)(((g >> 1) * 8 + r) * ROWB + (g & 1) * 16);

    float C[4][8][4];
    #pragma unroll
    for (int i = 0; i < 4; i++)
        #pragma unroll
        for (int j = 0; j < 8; j++)
            #pragma unroll
            for (int q = 0; q < 4; q++) C[i][j][q] = 0.f;

    auto loadA = [&](int chunk, int buf) {
        const unsigned char* sh = g_Ah + (size_t)(p * 32 + chunk) * (128 * ROWB);
        const unsigned char* sl = g_Al + (size_t)(p * 32 + chunk) * (128 * ROWB);
        uint32_t dh = sb + SM_A + buf * 20480;
        uint32_t dl = dh + 10240;
        #pragma unroll
        for (int t = 0; t < 3; t++) {
            int i = tid + t * 256;
            if (i < 640) {
                cp16(dh + i * 16, sh + i * 16);
                cp16(dl + i * 16, sl + i * 16);
            }
        }
    };
    // window rows r=0..8 -> ih = ta+rh-1+r; float s in row holds x at iw = s-2 (zeros outside)
    auto loadWin = [&](int chunk) {
        #pragma unroll
        for (int t = 0; t < 6; t++) {
            int i = tid + t * 256;
            if (i < ICPC * 9 * 18) {
                int icl = i / 162;
                int rem = i - icl * 162;
                int rr = rem / 18;
                int piece = rem - rr * 18;
                int ih = ta + rh - 1 + rr;
                bool rv = (unsigned)ih < HIN;
                int ihc = rv ? ih : 0;
                bool mid = (piece >= 1) && (piece <= 16);
                int iw0 = mid ? (piece - 1) * 2 : 0;
                const char* src = (const char*)x +
                    ((((size_t)b * IC + chunk * ICPC + icl) * HIN + ihc) * WIN_ + iw0) * 4;
                uint32_t dst = sb + SM_WIN + (icl * 9 + rr) * (WIN_ROWF * 4) + piece * 8;
                cp8z(dst, src, (rv && mid) ? 8 : 0);
            }
        }
    };
    // B[n][k] rows (ROWB stride): thread n expands 8 ic x 4 taps, hi/lo bf16 split
    auto expand = [&](int buf) {
        const int n = tid, a_l = n >> 5, c_l = n & 31;
        const int q0 = c_l + rw + 1;
        const float* winf = (const float*)(smem + SM_WIN);
        char* bh = smem + SM_B + buf * 40960 + n * ROWB;
        char* bl = bh + 20480;
        #pragma unroll
        for (int icl = 0; icl < ICPC; icl++) {
            const float* w0 = winf + (icl * 9 + a_l) * WIN_ROWF + q0;
            float v00 = w0[0], v01 = w0[1];
            float v10 = w0[WIN_ROWF], v11 = w0[WIN_ROWF + 1];
            uint32_t h01 = bf16x2_of(v00, v01);
            uint32_t h23 = bf16x2_of(v10, v11);
            float r00 = __uint_as_float(h01 << 16);
            float r01 = __uint_as_float(h01 & 0xFFFF0000u);
            float r10 = __uint_as_float(h23 << 16);
            float r11 = __uint_as_float(h23 & 0xFFFF0000u);
            uint32_t l01 = bf16x2_of(v00 - r00, v01 - r01);
            uint32_t l23 = bf16x2_of(v10 - r10, v11 - r11);
            *(uint2*)(bh + icl * 8) = make_uint2(h01, h23);
            *(uint2*)(bl + icl * 8) = make_uint2(l01, l23);
        }
    };
    auto compute = [&](int buf) {
        uint32_t Ah = sb + SM_A + buf * 20480 + wm * (64 * ROWB) + a_lane;
        uint32_t Al = Ah + 10240;
        uint32_t Bh = sb + SM_B + buf * 40960 + wn * (64 * ROWB) + b_lane;
        uint32_t Bl = Bh + 20480;
        #pragma unroll
        for (int ks = 0; ks < 2; ks++) {
            uint32_t ah[4][4], al[4][4];
            #pragma unroll
            for (int tm = 0; tm < 4; tm++) {
                LDSM4(ah[tm], Ah + tm * (16 * ROWB) + ks * 32);
                LDSM4(al[tm], Al + tm * (16 * ROWB) + ks * 32);
            }
            #pragma unroll
            for (int tn = 0; tn < 4; tn++) {
                uint32_t bhf[4], blf[4];
                LDSM4(bhf, Bh + tn * (16 * ROWB) + ks * 32);
                LDSM4(blf, Bl + tn * (16 * ROWB) + ks * 32);
                #pragma unroll
                for (int tm = 0; tm < 4; tm++) {
                    #pragma unroll
                    for (int h = 0; h < 2; h++) {
                        float* c = C[tm][tn * 2 + h];
                        MMA(c, ah[tm], bhf[2 * h], bhf[2 * h + 1]);
                        MMA(c, ah[tm], blf[2 * h], blf[2 * h + 1]);
                        MMA(c, al[tm], bhf[2 * h], bhf[2 * h + 1]);
                    }
                }
            }
        }
    };

    // ---- prologue ----
    loadWin(0); loadA(0, 0); cp_commit();
    cp_wait<0>(); __syncthreads();
    expand(0);
    __syncthreads();
    loadWin(1); loadA(1, 1); cp_commit();

    // ---- mainloop ----
    for (int i = 0; i < NCHUNK; i++) {
        compute(i & 1);
        if (i + 1 < NCHUNK) {
            cp_wait<0>(); __syncthreads();
            expand((i + 1) & 1);
            __syncthreads();
            if (i + 2 < NCHUNK) { loadWin(i + 2); loadA(i + 2, i & 1); cp_commit(); }
        }
    }

    // ---- epilogue: scatter C + bias ----
    {
        const int row = lane >> 2, qc = lane & 3;
        #pragma unroll
        for (int tm = 0; tm < 4; tm++) {
            const int oc0 = wm * 64 + tm * 16 + row;
            const float bv0 = bias[oc0];
            const float bv1 = bias[oc0 + 8];
            #pragma unroll
            for (int f = 0; f < 8; f++) {
                const int n = wn * 64 + f * 8 + 2 * qc;
                const int a_l = n >> 5, c_l = n & 31;
                const int oh = 2 * (ta + a_l) + rh;
                const int ow = 2 * c_l + rw;
                float* yp = y + (((size_t)b * OC + oc0) * 64 + oh) * 64 + ow;
                yp[0] = C[tm][f][0] + bv0;
                yp[2] = C[tm][f][1] + bv0;
                float* yp8 = yp + 8 * 64 * 64;
                yp8[0] = C[tm][f][2] + bv1;
                yp8[2] = C[tm][f][3] + bv1;
            }
        }
    }
}

extern "C" void kernel_launch(void* const* d_in, const int* in_sizes, int n_in,
                              void* d_out, int out_size) {
    const float* x    = (const float*)d_in[0];
    const float* W    = (const float*)d_in[1];
    const float* bias = (const float*)d_in[2];
    float* y = (float*)d_out;

    cudaFuncSetAttribute(tconv_hmma, cudaFuncAttributeMaxDynamicSharedMemorySize, SMEM_TOTAL);

    wt_kernel<<<2048, 256>>>(W);

    dim3 grid(4, NB, 4);
    tconv_hmma<<<grid, 256, SMEM_TOTAL>>>(x, bias, y);
}

// round 12
// speedup vs baseline: 3.3784x; 1.2821x over previous
#include <cuda_runtime.h>
#include <cuda_bf16.h>
#include <cstdint>

#define IC    256
#define OC    128
#define HIN   32
#define WIN_  32
#define NB    32
#define ICPC  8
#define NCHUNK 32
#define ROWB  80          // bytes per k-row: 32 bf16 = 64B + 16B pad (conflict-free ldmatrix)

// ---- dynamic SMEM layout (bytes) ----
// A: [buf][hl][128][ROWB]  buf*20480 + hl*10240   -> 40960
// B: [buf][hl][128][ROWB]  buf*20480 + hl*10240   -> 40960
// WIN: 8 ic x 5 rows x 36 floats                  -> 5760
#define SM_A    0
#define SM_B    40960
#define SM_WIN  81920
#define WIN_ROWF 36
#define SMEM_TOTAL (SM_WIN + ICPC*5*WIN_ROWF*4)   // 87680  (2 CTAs/SM: 175360 < 227KB)

// Pre-laid-out A: [p][chunk][128 oc][ROWB]  (k-major bf16 rows, 16B tail pad unused)
__device__ __align__(16) unsigned char g_Ah[4 * 32 * 128 * ROWB];
__device__ __align__(16) unsigned char g_Al[4 * 32 * 128 * ROWB];

// ---------------- asm helpers ----------------
__device__ __forceinline__ uint32_t smem_u32(const void* p) {
    uint32_t a;
    asm("{ .reg .u64 t; cvta.to.shared.u64 t, %1; cvt.u32.u64 %0, t; }" : "=r"(a) : "l"(p));
    return a;
}
__device__ __forceinline__ void cp16(uint32_t d, const void* s) {
    asm volatile("cp.async.cg.shared.global [%0], [%1], 16;" :: "r"(d), "l"(s) : "memory");
}
__device__ __forceinline__ void cp8z(uint32_t d, const void* s, int sz) {
    asm volatile("cp.async.ca.shared.global [%0], [%1], 8, %2;" :: "r"(d), "l"(s), "r"(sz) : "memory");
}
__device__ __forceinline__ void cp_commit() { asm volatile("cp.async.commit_group;" ::: "memory"); }
template <int N> __device__ __forceinline__ void cp_wait() {
    asm volatile("cp.async.wait_group %0;" :: "n"(N) : "memory");
}
__device__ __forceinline__ uint32_t bf16x2_of(float lo, float hi) {
    uint32_t r;
    asm("cvt.rn.bf16x2.f32 %0, %1, %2;" : "=r"(r) : "f"(hi), "f"(lo));
    return r;
}
#define LDSM4(r, a)                                                              \
    asm volatile("ldmatrix.sync.aligned.m8n8.x4.shared.b16 {%0,%1,%2,%3}, [%4];" \
                 : "=r"((r)[0]), "=r"((r)[1]), "=r"((r)[2]), "=r"((r)[3])        \
                 : "r"(a))
#define MMA(c, a, b0, b1)                                                        \
    asm volatile("mma.sync.aligned.m16n8k16.row.col.f32.bf16.bf16.f32 "          \
                 "{%0,%1,%2,%3},{%4,%5,%6,%7},{%8,%9},{%0,%1,%2,%3};"            \
                 : "+f"((c)[0]), "+f"((c)[1]), "+f"((c)[2]), "+f"((c)[3])        \
                 : "r"((a)[0]), "r"((a)[1]), "r"((a)[2]), "r"((a)[3]),           \
                   "r"(b0), "r"(b1))

// ---------------- weight transform ----------------
// A[oc][k] = W[oc][ck*8+icl][2j+rh][2i+rw], k = icl*4 + (j*2+i). hi/lo bf16 split.
__global__ void wt_kernel(const float* __restrict__ W) {
    int idx = blockIdx.x * blockDim.x + threadIdx.x;   // 2^19
    int k  = idx & 31;
    int oc = (idx >> 5) & 127;
    int ck = (idx >> 12) & 31;
    int p  = idx >> 17;
    int tap = k & 3, icl = k >> 2;
    int ic = ck * ICPC + icl;
    int kh = 2 * (tap >> 1) + (p >> 1);
    int kw = 2 * (tap & 1) + (p & 1);
    float v = W[((oc * IC + ic) * 4 + kh) * 4 + kw];
    __nv_bfloat16 h = __float2bfloat16(v);
    __nv_bfloat16 l = __float2bfloat16(v - __bfloat162float(h));
    size_t off = ((size_t)(p * 32 + ck) * 128 + oc) * ROWB + k * 2;
    *(__nv_bfloat16*)(g_Ah + off) = h;
    *(__nv_bfloat16*)(g_Al + off) = l;
}

// ---------------- main kernel ----------------
// grid (8 a-blocks, 32 batches, 4 parities) = 1024 CTAs, 2 CTAs/SM.
// CTA: D[oc=128][n=128], n = a_l*32 + c_l, a_l in 0..3 (ta = blockIdx.x*4).
// 8 warps: wm = warp&1 (64-oc half), wn = warp>>1 (32-n quarter = one a-row).
__global__ __launch_bounds__(256, 2)
void tconv_hmma(const float* __restrict__ x,
                const float* __restrict__ bias,
                float* __restrict__ y) {
    extern __shared__ char smem[];
    const uint32_t sb = smem_u32(smem);
    const int tid = threadIdx.x;
    const int warp = tid >> 5, lane = tid & 31;
    const int wm = warp & 1, wn = warp >> 1;
    const int p = blockIdx.z, b = blockIdx.y;
    const int rh = p >> 1, rw = p & 1;
    const int ta = blockIdx.x * 4;

    const int g = lane >> 3, r = lane & 7;
    const uint32_t a_lane = (uint32_t)(((g & 1) * 8 + r) * ROWB + (g >> 1) * 16);
    const uint32_t b_lane = (uint32_t)(((g >> 1) * 8 + r) * ROWB + (g & 1) * 16);

    float C[4][4][4];   // [tm: 16-oc][f: 8-n][frag]
    #pragma unroll
    for (int i = 0; i < 4; i++)
        #pragma unroll
        for (int j = 0; j < 4; j++)
            #pragma unroll
            for (int q = 0; q < 4; q++) C[i][j][q] = 0.f;

    auto loadA = [&](int chunk, int buf) {
        const unsigned char* sh = g_Ah + (size_t)(p * 32 + chunk) * (128 * ROWB);
        const unsigned char* sl = g_Al + (size_t)(p * 32 + chunk) * (128 * ROWB);
        uint32_t dh = sb + SM_A + buf * 20480;
        uint32_t dl = dh + 10240;
        #pragma unroll
        for (int t = 0; t < 3; t++) {
            int i = tid + t * 256;
            if (i < 640) {
                cp16(dh + i * 16, sh + i * 16);
                cp16(dl + i * 16, sl + i * 16);
            }
        }
    };
    // window rows r=0..4 -> ih = ta+rh-1+r; float s holds x at iw = s-2 (zeros outside)
    auto loadWin = [&](int chunk) {
        #pragma unroll
        for (int t = 0; t < 3; t++) {
            int i = tid + t * 256;
            if (i < ICPC * 5 * 18) {
                int icl = i / 90;
                int rem = i - icl * 90;
                int rr = rem / 18;
                int piece = rem - rr * 18;
                int ih = ta + rh - 1 + rr;
                bool rv = (unsigned)ih < HIN;
                int ihc = rv ? ih : 0;
                bool mid = (piece >= 1) && (piece <= 16);
                int iw0 = mid ? (piece - 1) * 2 : 0;
                const char* src = (const char*)x +
                    ((((size_t)b * IC + chunk * ICPC + icl) * HIN + ihc) * WIN_ + iw0) * 4;
                uint32_t dst = sb + SM_WIN + (icl * 5 + rr) * (WIN_ROWF * 4) + piece * 8;
                cp8z(dst, src, (rv && mid) ? 8 : 0);
            }
        }
    };
    // B[n][k] rows (ROWB stride): 2 threads per n, each expands 4 ic (hi/lo split)
    auto expand = [&](int buf) {
        const int n = tid & 127, half = tid >> 7;
        const int a_l = n >> 5, c_l = n & 31;
        const int q0 = c_l + rw + 1;
        const float* winf = (const float*)(smem + SM_WIN);
        char* bh = smem + SM_B + buf * 20480 + n * ROWB;
        char* bl = bh + 10240;
        #pragma unroll
        for (int t = 0; t < 4; t++) {
            int icl = half * 4 + t;
            const float* w0 = winf + (icl * 5 + a_l) * WIN_ROWF + q0;
            float v00 = w0[0], v01 = w0[1];
            float v10 = w0[WIN_ROWF], v11 = w0[WIN_ROWF + 1];
            uint32_t h01 = bf16x2_of(v00, v01);
            uint32_t h23 = bf16x2_of(v10, v11);
            float r00 = __uint_as_float(h01 << 16);
            float r01 = __uint_as_float(h01 & 0xFFFF0000u);
            float r10 = __uint_as_float(h23 << 16);
            float r11 = __uint_as_float(h23 & 0xFFFF0000u);
            uint32_t l01 = bf16x2_of(v00 - r00, v01 - r01);
            uint32_t l23 = bf16x2_of(v10 - r10, v11 - r11);
            *(uint2*)(bh + icl * 8) = make_uint2(h01, h23);
            *(uint2*)(bl + icl * 8) = make_uint2(l01, l23);
        }
    };
    auto compute = [&](int buf) {
        uint32_t Ah = sb + SM_A + buf * 20480 + wm * (64 * ROWB) + a_lane;
        uint32_t Al = Ah + 10240;
        uint32_t Bh = sb + SM_B + buf * 20480 + wn * (32 * ROWB) + b_lane;
        uint32_t Bl = Bh + 10240;
        #pragma unroll
        for (int ks = 0; ks < 2; ks++) {
            uint32_t ah[4][4], al[4][4];
            #pragma unroll
            for (int tm = 0; tm < 4; tm++) {
                LDSM4(ah[tm], Ah + tm * (16 * ROWB) + ks * 32);
                LDSM4(al[tm], Al + tm * (16 * ROWB) + ks * 32);
            }
            #pragma unroll
            for (int tn = 0; tn < 2; tn++) {
                uint32_t bhf[4], blf[4];
                LDSM4(bhf, Bh + tn * (16 * ROWB) + ks * 32);
                LDSM4(blf, Bl + tn * (16 * ROWB) + ks * 32);
                #pragma unroll
                for (int tm = 0; tm < 4; tm++) {
                    #pragma unroll
                    for (int h = 0; h < 2; h++) {
                        float* c = C[tm][tn * 2 + h];
                        MMA(c, ah[tm], bhf[2 * h], bhf[2 * h + 1]);
                        MMA(c, ah[tm], blf[2 * h], blf[2 * h + 1]);
                        MMA(c, al[tm], bhf[2 * h], bhf[2 * h + 1]);
                    }
                }
            }
        }
    };

    // ---- prologue ----
    loadWin(0); loadA(0, 0); cp_commit();
    cp_wait<0>(); __syncthreads();
    expand(0);
    __syncthreads();
    loadWin(1); loadA(1, 1); cp_commit();

    // ---- mainloop ----
    for (int i = 0; i < NCHUNK; i++) {
        compute(i & 1);
        if (i + 1 < NCHUNK) {
            cp_wait<0>(); __syncthreads();
            expand((i + 1) & 1);
            __syncthreads();
            if (i + 2 < NCHUNK) { loadWin(i + 2); loadA(i + 2, i & 1); cp_commit(); }
        }
    }

    // ---- epilogue: scatter C + bias ----
    {
        const int row = lane >> 2, qc = lane & 3;
        const int oh = 2 * (ta + wn) + rh;               // a_l == wn for this warp
        #pragma unroll
        for (int tm = 0; tm < 4; tm++) {
            const int oc0 = wm * 64 + tm * 16 + row;
            const float bv0 = bias[oc0];
            const float bv1 = bias[oc0 + 8];
            #pragma unroll
            for (int f = 0; f < 4; f++) {
                const int c_l = f * 8 + 2 * qc;
                const int ow = 2 * c_l + rw;
                float* yp = y + (((size_t)b * OC + oc0) * 64 + oh) * 64 + ow;
                yp[0] = C[tm][f][0] + bv0;
                yp[2] = C[tm][f][1] + bv0;
                float* yp8 = yp + 8 * 64 * 64;
                yp8[0] = C[tm][f][2] + bv1;
                yp8[2] = C[tm][f][3] + bv1;
            }
        }
    }
}

extern "C" void kernel_launch(void* const* d_in, const int* in_sizes, int n_in,
                              void* d_out, int out_size) {
    const float* x    = (const float*)d_in[0];
    const float* W    = (const float*)d_in[1];
    const float* bias = (const float*)d_in[2];
    float* y = (float*)d_out;

    cudaFuncSetAttribute(tconv_hmma, cudaFuncAttributeMaxDynamicSharedMemorySize, SMEM_TOTAL);

    wt_kernel<<<2048, 256>>>(W);

    dim3 grid(8, NB, 4);
    tconv_hmma<<<grid, 256, SMEM_TOTAL>>>(x, bias, y);
}